// round 3
// baseline (speedup 1.0000x reference)
#include <cuda_runtime.h>
#include <math.h>

// Problem constants
#define KK 64
#define DD 64
#define BB 16
#define NTOK 16384
#define TT 64                        // tokens per chunk
#define NCHUNK_TOTAL (BB * NTOK / TT)   // 4096 chunks
#define GRID 296                     // persistent: 148 SMs x occ 2, single wave
#define NTHREADS 256
#define PSIZE (KK + 2 * KK * DD)     // 8256 partial floats per slot

#define FSTRIDE 132                  // f_sh row stride (floats, 16B aligned rows)
#define LSTRIDE 66                   // logits/Q row stride
#define LOG2E 1.4426950408889634f
#define LN2PI 1.8378770664093453f

// smem layout (floats): W[8192] | f[64*132] | L[64*66] | c[64] | stage[4096]
#define SM_W 0
#define SM_F 8192
#define SM_L (SM_F + 64 * FSTRIDE)           // 16640
#define SM_C (SM_L + 64 * LSTRIDE)           // 20864
#define SM_STAGE (SM_C + 64)                 // 20928
#define SMEM_FLOATS (SM_STAGE + 4096)        // 25024
#define SMEM_BYTES (SMEM_FLOATS * 4)         // 100096

__device__ float g_scratch[GRID * 2 * PSIZE];
__device__ int   g_tag[GRID * 2];
__device__ int   g_cnt = 0;
__device__ int   g_cnt2 = 0;

// ---------------- packed f32x2 helpers (sm_100+) ----------------
__device__ __forceinline__ void fma2(unsigned long long &d,
                                     unsigned long long a,
                                     unsigned long long b) {
    asm("fma.rn.f32x2 %0, %1, %2, %0;" : "+l"(d) : "l"(a), "l"(b));
}
__device__ __forceinline__ unsigned long long pack2(float x) {
    unsigned long long r;
    asm("mov.b64 %0, {%1, %1};" : "=l"(r) : "f"(x));
    return r;
}
__device__ __forceinline__ float2 unpk(unsigned long long v) {
    float2 r;
    asm("mov.b64 {%0, %1}, %2;" : "=f"(r.x), "=f"(r.y) : "l"(v));
    return r;
}
__device__ __forceinline__ float ex2f(float x) {
    float r;
    asm("ex2.approx.f32 %0, %1;" : "=f"(r) : "f"(x));
    return r;
}
__device__ __forceinline__ void cpasync16(float* dst_sh, const float* src) {
    unsigned saddr = (unsigned)__cvta_generic_to_shared(dst_sh);
    asm volatile("cp.async.cg.shared.global [%0], [%1], 16;" :: "r"(saddr), "l"(src));
}
__device__ __forceinline__ void cpcommit() { asm volatile("cp.async.commit_group;"); }
__device__ __forceinline__ void cpwait0()  { asm volatile("cp.async.wait_group 0;"); }

// ---------------- single fused persistent kernel ------------------
extern __shared__ float smem[];

__global__ __launch_bounds__(NTHREADS, 2)
void fv_fused_kernel(const float* __restrict__ x,
                     const float* __restrict__ pi,
                     const float* __restrict__ mu,
                     const float* __restrict__ var,
                     float* __restrict__ out) {
    float* W_sh  = smem + SM_W;
    float* f_sh  = smem + SM_F;
    float* L_sh  = smem + SM_L;
    float* c_sh  = smem + SM_C;
    float* stage = smem + SM_STAGE;

    const int tid = threadIdx.x;
    const int bid = blockIdx.x;

    // chunk range for this CTA
    const int s_lo = (bid * NCHUNK_TOTAL) / GRID;
    const int s_hi = ((bid + 1) * NCHUNK_TOTAL) / GRID;

    // ---- prologue: stage first chunk (latency overlapped with prep) ----
    {
        const float* src = x + (size_t)s_lo * (TT * DD);
#pragma unroll
        for (int it = 0; it < 4; it++)
            cpasync16(stage + (tid + NTHREADS * it) * 4, src + (tid + NTHREADS * it) * 4);
        cpcommit();
    }

    // ---- prep: fold weights/constants into smem (per-CTA) ----
    // W[k,d] = -0.5/var*log2e ; W[k,64+d] = mu/var*log2e
    for (int i = tid; i < KK * 128; i += NTHREADS) {
        int k = i >> 7, j = i & 127, d = j & 63;
        float v = var[k * DD + d];
        float iv = __frcp_rn(v);
        float w = (j < 64) ? (-0.5f * iv * LOG2E) : (mu[k * DD + d] * iv * LOG2E);
        W_sh[i] = w;
    }
    {   // c[k] = (-0.5*(D ln2pi + sum(log v + m^2/v)) + ln pi)*log2e
        int k = tid >> 2, seg = tid & 3;
        float part = 0.f;
#pragma unroll 4
        for (int d = seg * 16; d < seg * 16 + 16; d++) {
            float v = var[k * DD + d];
            float m = mu[k * DD + d];
            part += __logf(v) + m * m * __frcp_rn(v);
        }
        part += __shfl_xor_sync(0xffffffffu, part, 1);
        part += __shfl_xor_sync(0xffffffffu, part, 2);
        if (seg == 0)
            c_sh[k] = (-0.5f * (64.0f * LN2PI + part) + __logf(pi[k])) * LOG2E;
    }

    // phase-3 accumulators: thread (ki, di) owns k in {ki+16i}, d quad 4di..4di+3
    const int ki = tid >> 4;
    const int di = tid & 15;
    unsigned long long aqx[4][2], aqx2[4][2];
    float qsum[4];
#pragma unroll
    for (int i = 0; i < 4; i++) {
        aqx[i][0] = 0ull; aqx[i][1] = 0ull;
        aqx2[i][0] = 0ull; aqx2[i][1] = 0ull;
        qsum[i] = 0.f;
    }
    int slot = 0;
    int cur_b = s_lo >> 8;      // 256 chunks per batch

    // phase-1 mapping: tokens tg+16*t4, k = 4*kg+k4
    const int tg = tid & 15;
    const int kg = tid >> 4;

    for (int c = s_lo; c < s_hi; c++) {
        cpwait0();
        __syncthreads();   // stage complete everywhere; f_sh/L_sh free; W ready

        // ---- phase 0: f = [x^2 | x] from stage into f_sh ----
#pragma unroll
        for (int it = 0; it < 4; it++) {
            int f4 = tid + NTHREADS * it;       // 0..1023
            int t  = f4 >> 4;
            int c4 = f4 & 15;
            float4 v = *(const float4*)(stage + f4 * 4);
            float* frow = f_sh + t * FSTRIDE;
            *(float4*)(frow + 64 + 4 * c4) = v;
            float4 s;
            s.x = v.x * v.x; s.y = v.y * v.y; s.z = v.z * v.z; s.w = v.w * v.w;
            *(float4*)(frow + 4 * c4) = s;
        }
        __syncthreads();

        // stage next chunk (lands during phases 1-3)
        if (c + 1 < s_hi) {
            const float* src = x + (size_t)(c + 1) * (TT * DD);
#pragma unroll
            for (int it = 0; it < 4; it++)
                cpasync16(stage + (tid + NTHREADS * it) * 4, src + (tid + NTHREADS * it) * 4);
            cpcommit();
        }

        // ---- phase 1: logits, 4 tokens x 4 k per thread, 128-bit LDS ----
        {
            unsigned long long acc[4][4];
#pragma unroll
            for (int a = 0; a < 4; a++)
#pragma unroll
                for (int cc = 0; cc < 4; cc++) acc[a][cc] = 0ull;

            const float* wbase = W_sh + (kg * 4) * 128;
#pragma unroll 4
            for (int jp2 = 0; jp2 < 32; jp2++) {
                ulonglong2 fv[4], wv[4];
#pragma unroll
                for (int t4 = 0; t4 < 4; t4++)
                    fv[t4] = *(const ulonglong2*)(f_sh + (tg + 16 * t4) * FSTRIDE + 4 * jp2);
#pragma unroll
                for (int k4 = 0; k4 < 4; k4++)
                    wv[k4] = *(const ulonglong2*)(wbase + k4 * 128 + 4 * jp2);
#pragma unroll
                for (int t4 = 0; t4 < 4; t4++)
#pragma unroll
                    for (int k4 = 0; k4 < 4; k4++) {
                        fma2(acc[t4][k4], fv[t4].x, wv[k4].x);
                        fma2(acc[t4][k4], fv[t4].y, wv[k4].y);
                    }
            }
#pragma unroll
            for (int t4 = 0; t4 < 4; t4++) {
                int t = tg + 16 * t4;
#pragma unroll
                for (int k4 = 0; k4 < 4; k4++) {
                    int k = 4 * kg + k4;
                    float2 a = unpk(acc[t4][k4]);
                    L_sh[t * LSTRIDE + k] = a.x + a.y + c_sh[k];
                }
            }
        }
        __syncthreads();

        // ---- phase 2: softmax over K=64 per token (warp per 8 tokens) ----
        {
            const int wid = tid >> 5;
            const int lane = tid & 31;
#pragma unroll
            for (int t8 = 0; t8 < 8; t8++) {
                int t = wid * 8 + t8;
                float l0 = L_sh[t * LSTRIDE + lane];
                float l1 = L_sh[t * LSTRIDE + lane + 32];
                float m = fmaxf(l0, l1);
#pragma unroll
                for (int o = 16; o > 0; o >>= 1)
                    m = fmaxf(m, __shfl_xor_sync(0xffffffffu, m, o));
                float e0 = ex2f(l0 - m);
                float e1 = ex2f(l1 - m);
                float ssum = e0 + e1;
#pragma unroll
                for (int o = 16; o > 0; o >>= 1)
                    ssum += __shfl_xor_sync(0xffffffffu, ssum, o);
                float inv = __frcp_rn(ssum);
                L_sh[t * LSTRIDE + lane]      = e0 * inv;
                L_sh[t * LSTRIDE + lane + 32] = e1 * inv;
            }
        }
        __syncthreads();

        // ---- phase 3: accumulate Q_sum, Q^T x, Q^T x^2 ----
        {
#pragma unroll 2
            for (int t = 0; t < TT; t++) {
                const float* frow = f_sh + t * FSTRIDE;
                const float* lrow = L_sh + t * LSTRIDE;
                ulonglong2 xq = *(const ulonglong2*)(frow + 64 + 4 * di);
                ulonglong2 sq = *(const ulonglong2*)(frow + 4 * di);
#pragma unroll
                for (int i = 0; i < 4; i++) {
                    float q = lrow[ki + 16 * i];
                    unsigned long long q2 = pack2(q);
                    fma2(aqx[i][0], q2, xq.x);
                    fma2(aqx[i][1], q2, xq.y);
                    fma2(aqx2[i][0], q2, sq.x);
                    fma2(aqx2[i][1], q2, sq.y);
                    if (di == 0) qsum[i] += q;
                }
            }
        }

        // ---- flush partials at batch boundary / end of range ----
        int nb = (c + 1) >> 8;
        if (c + 1 == s_hi || nb != cur_b) {
            float* outp = g_scratch + (size_t)(bid * 2 + slot) * PSIZE;
            if (tid == 0) g_tag[bid * 2 + slot] = cur_b;
            if (di == 0) {
#pragma unroll
                for (int i = 0; i < 4; i++) outp[ki + 16 * i] = qsum[i];
            }
#pragma unroll
            for (int i = 0; i < 4; i++) {
                int k = ki + 16 * i;
                float2 v0 = unpk(aqx[i][0]);
                float2 v1 = unpk(aqx[i][1]);
                float4 o; o.x = v0.x; o.y = v0.y; o.z = v1.x; o.w = v1.y;
                *(float4*)(outp + 64 + k * 64 + 4 * di) = o;
                float2 w0 = unpk(aqx2[i][0]);
                float2 w1 = unpk(aqx2[i][1]);
                float4 o2; o2.x = w0.x; o2.y = w0.y; o2.z = w1.x; o2.w = w1.y;
                *(float4*)(outp + 64 + 4096 + k * 64 + 4 * di) = o2;
            }
#pragma unroll
            for (int i = 0; i < 4; i++) {
                aqx[i][0] = 0ull; aqx[i][1] = 0ull;
                aqx2[i][0] = 0ull; aqx2[i][1] = 0ull;
                qsum[i] = 0.f;
            }
            slot++;
            cur_b = nb;
        }
    }
    if (tid == 0) {
        for (int sl = slot; sl < 2; sl++) g_tag[bid * 2 + sl] = -1;
    }

    // ================= device-wide barrier (single wave) =================
    __syncthreads();
    if (tid == 0) {
        __threadfence();                       // release scratch + tags
        atomicAdd(&g_cnt, 1);
        while (((volatile int*)&g_cnt)[0] < GRID) __nanosleep(64);
        __threadfence();                       // acquire
    }
    __syncthreads();

    // ================= reduce + finalize (one elem per thread) ==========
    {
        int idx = bid * NTHREADS + tid;        // 0 .. 75775
        if (idx < BB * KK * DD) {
            int b  = idx >> 12;
            int kd = idx & 4095;
            int k  = kd >> 6;
            int d  = kd & 63;

            int i_lo = (GRID * b) / 16 - 1;       if (i_lo < 0) i_lo = 0;
            int i_hi = (GRID * (b + 1)) / 16 + 1; if (i_hi > GRID - 1) i_hi = GRID - 1;

            float qs = 0.f, qx = 0.f, qx2 = 0.f;
            for (int i = i_lo; i <= i_hi; i++) {
#pragma unroll
                for (int sl = 0; sl < 2; sl++) {
                    int sid = 2 * i + sl;
                    if (g_tag[sid] == b) {
                        const float* p = g_scratch + (size_t)sid * PSIZE;
                        qs  += p[k];
                        qx  += p[64 + kd];
                        qx2 += p[64 + 4096 + kd];
                    }
                }
            }
            const float invN = 1.0f / (float)NTOK;
            qs *= invN; qx *= invN; qx2 *= invN;

            float m = mu[kd];
            float v = var[kd];
            float* ob = out + (size_t)b * 8256;
            ob[64 + kd]        = qx - qs * m;
            ob[64 + 4096 + kd] = -qx2 - qs * m * m + qs * v + 2.0f * qx * m;
            if (d == 0) ob[k] = qs - pi[k];
        }
    }

    // ---- reset counters for next (graph-replayed) call ----
    __syncthreads();
    if (tid == 0) {
        int old = atomicAdd(&g_cnt2, 1);
        if (old == GRID - 1) {                 // last CTA: everyone passed barrier 1
            g_cnt = 0;
            g_cnt2 = 0;
            __threadfence();
        }
    }
}

// ---------------- launch -----------------------------------------
extern "C" void kernel_launch(void* const* d_in, const int* in_sizes, int n_in,
                              void* d_out, int out_size) {
    const float* x   = (const float*)d_in[0];
    const float* pi  = (const float*)d_in[1];
    const float* mu  = (const float*)d_in[2];
    const float* var = (const float*)d_in[3];
    float* out = (float*)d_out;

    cudaFuncSetAttribute(fv_fused_kernel,
                         cudaFuncAttributeMaxDynamicSharedMemorySize, SMEM_BYTES);

    fv_fused_kernel<<<GRID, NTHREADS, SMEM_BYTES>>>(x, pi, mu, var, out);
}